// round 15
// baseline (speedup 1.0000x reference)
#include <cuda_runtime.h>
#include <cuda_fp16.h>
#include <cstdint>

// Problem constants
#define M_ROWS   16425
#define M_PAD    16512            // 129 * 128
#define HID      2048
#define K_LEV    5
#define N_OUT    524289

// GEMM tiling: CTA 128x256, 8 warps of 64x64 (2m x 4n), BK=64, 3-stage, 1 CTA/SM
#define BM 128
#define BN 256
#define BK 64
#define NT (HID / BK)             // 32
#define NSTAGE 3
#define STRIDE 36                 // h2 per row: 32 data + 4 pad
#define A_H2 (BM * STRIDE)        // 4608
#define B_H2 (BN * STRIDE)        // 9216
#define STAGE_H2 (A_H2 + B_H2)    // 13824
#define SMEM_BYTES (STAGE_H2 * NSTAGE * 4)   // 165888

// ---------------------------------------------------------------------------
// Static device scratch
// ---------------------------------------------------------------------------
__device__ __align__(16) __half g_h0[(size_t)M_PAD * HID];
__device__ __align__(16) __half g_h1[(size_t)M_PAD * HID];
__device__ __align__(16) __half g_wh[3][(size_t)HID * HID];  // fp16, transposed [n][k]
__device__ float g_amg[16448];

// ---------------------------------------------------------------------------
// PTX helpers
// ---------------------------------------------------------------------------
__device__ __forceinline__ void cp_async16(void* smem, const void* gmem) {
    uint32_t s = (uint32_t)__cvta_generic_to_shared(smem);
    asm volatile("cp.async.cg.shared.global [%0], [%1], 16;\n" :: "r"(s), "l"(gmem));
}
__device__ __forceinline__ void cp_commit() {
    asm volatile("cp.async.commit_group;\n" ::);
}
__device__ __forceinline__ void ldsm_x4(uint32_t& r0, uint32_t& r1, uint32_t& r2,
                                        uint32_t& r3, uint32_t saddr) {
    asm volatile("ldmatrix.sync.aligned.m8n8.x4.shared.b16 {%0,%1,%2,%3}, [%4];"
                 : "=r"(r0), "=r"(r1), "=r"(r2), "=r"(r3) : "r"(saddr));
}
__device__ __forceinline__ void mma_f16(float* d, const uint32_t* a, const uint32_t* b) {
    asm volatile(
        "mma.sync.aligned.m16n8k16.row.col.f32.f16.f16.f32 "
        "{%0,%1,%2,%3}, {%4,%5,%6,%7}, {%8,%9}, {%0,%1,%2,%3};\n"
        : "+f"(d[0]), "+f"(d[1]), "+f"(d[2]), "+f"(d[3])
        : "r"(a[0]), "r"(a[1]), "r"(a[2]), "r"(a[3]), "r"(b[0]), "r"(b[1]));
}
__device__ __forceinline__ float h_round(float v) {
    return __half2float(__float2half_rn(v));
}

// ---------------------------------------------------------------------------
// Fused weight transpose + fp16 convert for all 3 layers (z selects layer)
// ---------------------------------------------------------------------------
__global__ void transpose_half3(const float* __restrict__ in0,
                                const float* __restrict__ in1,
                                const float* __restrict__ in2,
                                __half* __restrict__ outbase) {
    const float* in = (blockIdx.z == 0) ? in0 : (blockIdx.z == 1) ? in1 : in2;
    __half* out = outbase + (size_t)blockIdx.z * HID * HID;
    __shared__ float t[32][33];
    int bx = blockIdx.x * 32, by = blockIdx.y * 32;
#pragma unroll
    for (int i = 0; i < 32; i += 8)
        t[threadIdx.y + i][threadIdx.x] = in[(size_t)(by + threadIdx.y + i) * HID + bx + threadIdx.x];
    __syncthreads();
#pragma unroll
    for (int i = 0; i < 32; i += 8)
        out[(size_t)(bx + threadIdx.y + i) * HID + by + threadIdx.x] =
            __float2half_rn(t[threadIdx.x][threadIdx.y + i]);
}

// ---------------------------------------------------------------------------
// Layer 0 (register-cached weights) + fused zero of g_amg.
// ---------------------------------------------------------------------------
#define L0_ROWS 32
__global__ void __launch_bounds__(256)
layer0_kernel(const float* __restrict__ xs,
              const float* __restrict__ w0,
              const float* __restrict__ b0) {
    // fused: zero the GEMV accumulator (516 blocks x 256 threads cover 16448)
    int gid = blockIdx.x * blockDim.x + threadIdx.x;
    if (gid < 16448) g_amg[gid] = 0.0f;

    const int jc = threadIdx.x * 8;
    float w[8], b[8];
#pragma unroll
    for (int q = 0; q < 2; q++) {
        *(float4*)(w + 4 * q) = *(const float4*)(w0 + jc + 4 * q);
        *(float4*)(b + 4 * q) = *(const float4*)(b0 + jc + 4 * q);
    }
    const int r0 = blockIdx.x * L0_ROWS;
#pragma unroll 1
    for (int r = r0; r < r0 + L0_ROWS; r++) {
        __half2 v[4];
        if (r < M_ROWS) {
            const float x = __ldg(&xs[r]);
#pragma unroll
            for (int q = 0; q < 4; q++)
                v[q] = __floats2half2_rn(fmaxf(fmaf(x, w[2 * q], b[2 * q]), 0.0f),
                                         fmaxf(fmaf(x, w[2 * q + 1], b[2 * q + 1]), 0.0f));
        } else {
#pragma unroll
            for (int q = 0; q < 4; q++) v[q] = __float2half2_rn(0.0f);
        }
        *(uint4*)(g_h0 + (size_t)r * HID + jc) = *(uint4*)v;
    }
}

// ---------------------------------------------------------------------------
// Fused fp16 GEMM + bias + ReLU  (exact Round-13 configuration)
// fuse==0: store C (half).  fuse==1: no store; accumulate dot with w4 into g_amg.
// ---------------------------------------------------------------------------
__global__ void __launch_bounds__(256, 1)
gemm_f16_kernel(const __half* __restrict__ Wt,
                const float* __restrict__ bias,
                const float* __restrict__ w4,
                int sel, int fuse) {
    const __half* __restrict__ A = sel ? g_h1 : g_h0;
    __half* __restrict__ C       = sel ? g_h0 : g_h1;

    extern __shared__ uint32_t sm[];   // h2 units

    const int t    = threadIdx.x;
    const int lane = t & 31;
    const int wid  = t >> 5;
    const int wm   = wid & 1;
    const int wn   = wid >> 1;
    const int g    = lane >> 2;
    const int tg   = lane & 3;

    const int bm = blockIdx.y * BM;
    const int bn = blockIdx.x * BN;

    float acc[4][8][4];
#pragma unroll
    for (int i = 0; i < 4; i++)
#pragma unroll
        for (int j = 0; j < 8; j++)
#pragma unroll
            for (int r = 0; r < 4; r++) acc[i][j][r] = 0.0f;

    const int a_idx = (wm * 64 + (lane & 15)) * STRIDE + ((lane >> 4) << 2);
    const int b_idx = (wn * 64 + ((lane >> 4) << 3) + (lane & 7)) * STRIDE
                      + (((lane >> 3) & 1) << 2);

    auto load_a_chunk = [&](int kt, int stage, int it) {
        uint32_t* As = sm + stage * STAGE_H2;
        const int kh0 = kt * (BK / 2);
        int chunk = t + it * 256;
        int row = chunk >> 3, c = chunk & 7;
        cp_async16(&As[row * STRIDE + c * 4],
                   (const __half2*)A + (size_t)(bm + row) * (HID / 2) + kh0 + c * 4);
    };
    auto load_b_chunk = [&](int kt, int stage, int it) {
        uint32_t* Bs = sm + stage * STAGE_H2 + A_H2;
        const int kh0 = kt * (BK / 2);
        int chunk = t + it * 256;
        int row = chunk >> 3, c = chunk & 7;
        cp_async16(&Bs[row * STRIDE + c * 4],
                   (const __half2*)Wt + (size_t)(bn + row) * (HID / 2) + kh0 + c * 4);
    };
    auto load_tile = [&](int kt, int stage) {
#pragma unroll
        for (int it = 0; it < 4; it++) load_a_chunk(kt, stage, it);
#pragma unroll
        for (int it = 0; it < 8; it++) load_b_chunk(kt, stage, it);
        cp_commit();
    };

    auto step = [&](int kt, int stage) {
        asm volatile("cp.async.wait_group 1;\n" ::);
        __syncthreads();
        const int pstage = (stage == 0) ? 2 : stage - 1;
        const bool pf = (kt + 2 < NT);

        const int sbase = stage * STAGE_H2;
        const uint32_t a_addr0 = (uint32_t)__cvta_generic_to_shared(sm + sbase + a_idx);
        const uint32_t b_addr0 = (uint32_t)__cvta_generic_to_shared(sm + sbase + A_H2 + b_idx);

#pragma unroll
        for (int kk = 0; kk < 4; kk++) {
            const uint32_t koff = kk * 8 * 4;
            uint32_t af[4][4];
            uint32_t bf[4][4];
#pragma unroll
            for (int tm = 0; tm < 4; tm++)
                ldsm_x4(af[tm][0], af[tm][1], af[tm][2], af[tm][3],
                        a_addr0 + koff + tm * (16 * STRIDE * 4));
#pragma unroll
            for (int p = 0; p < 4; p++)
                ldsm_x4(bf[p][0], bf[p][1], bf[p][2], bf[p][3],
                        b_addr0 + koff + p * (16 * STRIDE * 4));
            if (pf) {
                load_a_chunk(kt + 2, pstage, kk);
                load_b_chunk(kt + 2, pstage, kk * 2);
                load_b_chunk(kt + 2, pstage, kk * 2 + 1);
            }
#pragma unroll
            for (int tm = 0; tm < 4; tm++)
#pragma unroll
                for (int tn = 0; tn < 8; tn++)
                    mma_f16(acc[tm][tn], af[tm], &bf[tn >> 1][(tn & 1) * 2]);
        }
        cp_commit();
    };

    load_tile(0, 0);
    load_tile(1, 1);

#pragma unroll 1
    for (int kt = 0; kt < 30; kt += 3) {
        step(kt,     0);
        step(kt + 1, 1);
        step(kt + 2, 2);
    }
    step(30, 0);
    step(31, 1);

    if (!fuse) {
#pragma unroll
        for (int tn = 0; tn < 8; tn++) {
            int c0 = bn + wn * 64 + tn * 8 + 2 * tg;
            float bv0 = __ldg(&bias[c0]);
            float bv1 = __ldg(&bias[c0 + 1]);
#pragma unroll
            for (int tm = 0; tm < 4; tm++) {
                int r0 = bm + wm * 64 + tm * 16 + g;
                __half2 v0 = __floats2half2_rn(fmaxf(acc[tm][tn][0] + bv0, 0.0f),
                                               fmaxf(acc[tm][tn][1] + bv1, 0.0f));
                __half2 v1 = __floats2half2_rn(fmaxf(acc[tm][tn][2] + bv0, 0.0f),
                                               fmaxf(acc[tm][tn][3] + bv1, 0.0f));
                *(__half2*)(C + (size_t)r0 * HID + c0) = v0;
                *(__half2*)(C + (size_t)(r0 + 8) * HID + c0) = v1;
            }
        }
    } else {
#pragma unroll
        for (int tm = 0; tm < 4; tm++) {
            float d0 = 0.0f, d1 = 0.0f;
#pragma unroll
            for (int tn = 0; tn < 8; tn++) {
                int c0 = bn + wn * 64 + tn * 8 + 2 * tg;
                float bv0 = __ldg(&bias[c0]);
                float bv1 = __ldg(&bias[c0 + 1]);
                float wv0 = __ldg(&w4[c0]);
                float wv1 = __ldg(&w4[c0 + 1]);
                d0 = fmaf(h_round(fmaxf(acc[tm][tn][0] + bv0, 0.0f)), wv0, d0);
                d0 = fmaf(h_round(fmaxf(acc[tm][tn][1] + bv1, 0.0f)), wv1, d0);
                d1 = fmaf(h_round(fmaxf(acc[tm][tn][2] + bv0, 0.0f)), wv0, d1);
                d1 = fmaf(h_round(fmaxf(acc[tm][tn][3] + bv1, 0.0f)), wv1, d1);
            }
            d0 += __shfl_xor_sync(0xFFFFFFFFu, d0, 1);
            d0 += __shfl_xor_sync(0xFFFFFFFFu, d0, 2);
            d1 += __shfl_xor_sync(0xFFFFFFFFu, d1, 1);
            d1 += __shfl_xor_sync(0xFFFFFFFFu, d1, 2);
            if (tg == 0) {
                int r0 = bm + wm * 64 + tm * 16 + g;
                if (r0 < M_ROWS)     atomicAdd(&g_amg[r0], d0);
                if (r0 + 8 < M_ROWS) atomicAdd(&g_amg[r0 + 8], d1);
            }
        }
    }
}

// ---------------------------------------------------------------------------
// Single-kernel multigrid: evaluates all 5 interp+scatter levels functionally.
// V(L, p): output of level L at position p.
//   p odd & p in nbrs[L]  -> band value  relu(g_amg[8*(4-L)+j] + b4)
//   p odd otherwise       -> 0.5*(V(L-1, p/2) + V(L-1, p/2+1))
//   p even                -> V(L-1, p/2)
//   V(-1, q) = relu(g_amg[40+q] + b4)          (coarse Ah)
// Value-identical to the amg_fix + 5-level chain.
// ---------------------------------------------------------------------------
__device__ __forceinline__ float mg_fix(float x, float b) { return fmaxf(x + b, 0.0f); }

template <int L>
__device__ float mgV(int p, const int* __restrict__ nbrs, float b) {
    if (p & 1) {
#pragma unroll
        for (int j = 0; j < 8; j++)
            if (p == nbrs[L * 8 + j]) return mg_fix(g_amg[8 * (4 - L) + j], b);
        int h = p >> 1;
        return 0.5f * (mgV<L - 1>(h, nbrs, b) + mgV<L - 1>(h + 1, nbrs, b));
    }
    return mgV<L - 1>(p >> 1, nbrs, b);
}
template <>
__device__ float mgV<-1>(int p, const int* __restrict__ nbrs, float b) {
    return mg_fix(g_amg[40 + p], b);
}

__global__ void mg_all(const int* __restrict__ nbrs,
                       const float* __restrict__ b4,
                       float* __restrict__ dout) {
    int p = blockIdx.x * blockDim.x + threadIdx.x;
    if (p >= N_OUT) return;
    dout[p] = mgV<4>(p, nbrs, b4[0]);
}

// ---------------------------------------------------------------------------
// Launch
// ---------------------------------------------------------------------------
extern "C" void kernel_launch(void* const* d_in, const int* in_sizes, int n_in,
                              void* d_out, int out_size) {
    const float *xs, *w0, *b0, *w1, *b1, *w2, *b2, *w3, *b3, *w4, *b4;
    const int* nbrs;

    if (n_in >= 2 && in_sizes[1] == 40) {
        xs   = (const float*)d_in[0];
        nbrs = (const int*)d_in[1];
        w0 = (const float*)d_in[4];  b0 = (const float*)d_in[5];
        w1 = (const float*)d_in[6];  b1 = (const float*)d_in[7];
        w2 = (const float*)d_in[8];  b2 = (const float*)d_in[9];
        w3 = (const float*)d_in[10]; b3 = (const float*)d_in[11];
        w4 = (const float*)d_in[12]; b4 = (const float*)d_in[13];
    } else {
        xs   = (const float*)d_in[0];
        w0 = (const float*)d_in[1];  b0 = (const float*)d_in[2];
        w1 = (const float*)d_in[3];  b1 = (const float*)d_in[4];
        w2 = (const float*)d_in[5];  b2 = (const float*)d_in[6];
        w3 = (const float*)d_in[7];  b3 = (const float*)d_in[8];
        w4 = (const float*)d_in[9];  b4 = (const float*)d_in[10];
        nbrs = (const int*)d_in[11];
    }

    void* p_wh;
    cudaGetSymbolAddress(&p_wh, g_wh);
    __half* wh0 = (__half*)p_wh;
    __half* wh1 = wh0 + (size_t)HID * HID;
    __half* wh2 = wh1 + (size_t)HID * HID;

    cudaFuncSetAttribute(gemm_f16_kernel,
                         cudaFuncAttributeMaxDynamicSharedMemorySize, SMEM_BYTES);

    // Fused weight transpose + fp16 convert (all 3 layers, one launch)
    {
        dim3 gr(HID / 32, HID / 32, 3), bl(32, 8);
        transpose_half3<<<gr, bl>>>(w1, w2, w3, wh0);
    }

    // Layer 0 -> g_h0 (fp16), fused g_amg zeroing
    layer0_kernel<<<M_PAD / L0_ROWS, 256>>>(xs, w0, b0);

    // Hidden GEMMs; third fuses the final-layer GEMV into its epilogue
    dim3 grid(HID / BN, M_PAD / BM);  // (8, 129)
    gemm_f16_kernel<<<grid, 256, SMEM_BYTES>>>(wh0, b1, nullptr, 0, 0); // h0 -> h1
    gemm_f16_kernel<<<grid, 256, SMEM_BYTES>>>(wh1, b2, nullptr, 1, 0); // h1 -> h0
    gemm_f16_kernel<<<grid, 256, SMEM_BYTES>>>(wh2, b3, w4,      0, 1); // h0 -> g_amg

    // Entire multigrid reconstruction (bias+relu fused) in ONE kernel
    mg_all<<<(N_OUT + 255) / 256, 256>>>(nbrs, b4, (float*)d_out);

    (void)out_size;
}

// round 16
// speedup vs baseline: 1.1192x; 1.1192x over previous
#include <cuda_runtime.h>
#include <cuda_fp16.h>
#include <cstdint>

// Problem constants
#define M_ROWS   16425
#define M_PAD    16512            // 129 * 128
#define HID      2048
#define K_LEV    5
#define N_OUT    524289

// GEMM tiling: CTA 128x256, 8 warps of 64x64 (2m x 4n), BK=64, 3-stage, 1 CTA/SM
#define BM 128
#define BN 256
#define BK 64
#define NT (HID / BK)             // 32
#define NSTAGE 3
#define STRIDE 36                 // h2 per row: 32 data + 4 pad
#define A_H2 (BM * STRIDE)        // 4608
#define B_H2 (BN * STRIDE)        // 9216
#define STAGE_H2 (A_H2 + B_H2)    // 13824
#define SMEM_BYTES (STAGE_H2 * NSTAGE * 4)   // 165888

// ---------------------------------------------------------------------------
// Static device scratch
// ---------------------------------------------------------------------------
__device__ __align__(16) __half g_h0[(size_t)M_PAD * HID];
__device__ __align__(16) __half g_h1[(size_t)M_PAD * HID];
__device__ __align__(16) __half g_wh[3][(size_t)HID * HID];  // fp16, transposed [n][k]
__device__ float g_amg[16448];

// ---------------------------------------------------------------------------
// PTX helpers
// ---------------------------------------------------------------------------
__device__ __forceinline__ void cp_async16(void* smem, const void* gmem) {
    uint32_t s = (uint32_t)__cvta_generic_to_shared(smem);
    asm volatile("cp.async.cg.shared.global [%0], [%1], 16;\n" :: "r"(s), "l"(gmem));
}
__device__ __forceinline__ void cp_commit() {
    asm volatile("cp.async.commit_group;\n" ::);
}
__device__ __forceinline__ void ldsm_x4(uint32_t& r0, uint32_t& r1, uint32_t& r2,
                                        uint32_t& r3, uint32_t saddr) {
    asm volatile("ldmatrix.sync.aligned.m8n8.x4.shared.b16 {%0,%1,%2,%3}, [%4];"
                 : "=r"(r0), "=r"(r1), "=r"(r2), "=r"(r3) : "r"(saddr));
}
__device__ __forceinline__ void mma_f16(float* d, const uint32_t* a, const uint32_t* b) {
    asm volatile(
        "mma.sync.aligned.m16n8k16.row.col.f32.f16.f16.f32 "
        "{%0,%1,%2,%3}, {%4,%5,%6,%7}, {%8,%9}, {%0,%1,%2,%3};\n"
        : "+f"(d[0]), "+f"(d[1]), "+f"(d[2]), "+f"(d[3])
        : "r"(a[0]), "r"(a[1]), "r"(a[2]), "r"(a[3]), "r"(b[0]), "r"(b[1]));
}
__device__ __forceinline__ float h_round(float v) {
    return __half2float(__float2half_rn(v));
}

// ---------------------------------------------------------------------------
// Fused weight transpose + fp16 convert for all 3 layers (z selects layer)
// ---------------------------------------------------------------------------
__global__ void transpose_half3(const float* __restrict__ in0,
                                const float* __restrict__ in1,
                                const float* __restrict__ in2,
                                __half* __restrict__ outbase) {
    const float* in = (blockIdx.z == 0) ? in0 : (blockIdx.z == 1) ? in1 : in2;
    __half* out = outbase + (size_t)blockIdx.z * HID * HID;
    __shared__ float t[32][33];
    int bx = blockIdx.x * 32, by = blockIdx.y * 32;
#pragma unroll
    for (int i = 0; i < 32; i += 8)
        t[threadIdx.y + i][threadIdx.x] = in[(size_t)(by + threadIdx.y + i) * HID + bx + threadIdx.x];
    __syncthreads();
#pragma unroll
    for (int i = 0; i < 32; i += 8)
        out[(size_t)(bx + threadIdx.y + i) * HID + by + threadIdx.x] =
            __float2half_rn(t[threadIdx.x][threadIdx.y + i]);
}

// ---------------------------------------------------------------------------
// Layer 0 (register-cached weights) + fused zero of g_amg.
// ---------------------------------------------------------------------------
#define L0_ROWS 32
__global__ void __launch_bounds__(256)
layer0_kernel(const float* __restrict__ xs,
              const float* __restrict__ w0,
              const float* __restrict__ b0) {
    int gid = blockIdx.x * blockDim.x + threadIdx.x;
    if (gid < 16448) g_amg[gid] = 0.0f;

    const int jc = threadIdx.x * 8;
    float w[8], b[8];
#pragma unroll
    for (int q = 0; q < 2; q++) {
        *(float4*)(w + 4 * q) = *(const float4*)(w0 + jc + 4 * q);
        *(float4*)(b + 4 * q) = *(const float4*)(b0 + jc + 4 * q);
    }
    const int r0 = blockIdx.x * L0_ROWS;
#pragma unroll 1
    for (int r = r0; r < r0 + L0_ROWS; r++) {
        __half2 v[4];
        if (r < M_ROWS) {
            const float x = __ldg(&xs[r]);
#pragma unroll
            for (int q = 0; q < 4; q++)
                v[q] = __floats2half2_rn(fmaxf(fmaf(x, w[2 * q], b[2 * q]), 0.0f),
                                         fmaxf(fmaf(x, w[2 * q + 1], b[2 * q + 1]), 0.0f));
        } else {
#pragma unroll
            for (int q = 0; q < 4; q++) v[q] = __float2half2_rn(0.0f);
        }
        *(uint4*)(g_h0 + (size_t)r * HID + jc) = *(uint4*)v;
    }
}

// ---------------------------------------------------------------------------
// Fused fp16 GEMM + bias + ReLU  (frozen Round-13 configuration)
// ---------------------------------------------------------------------------
__global__ void __launch_bounds__(256, 1)
gemm_f16_kernel(const __half* __restrict__ Wt,
                const float* __restrict__ bias,
                const float* __restrict__ w4,
                int sel, int fuse) {
    const __half* __restrict__ A = sel ? g_h1 : g_h0;
    __half* __restrict__ C       = sel ? g_h0 : g_h1;

    extern __shared__ uint32_t sm[];   // h2 units

    const int t    = threadIdx.x;
    const int lane = t & 31;
    const int wid  = t >> 5;
    const int wm   = wid & 1;
    const int wn   = wid >> 1;
    const int g    = lane >> 2;
    const int tg   = lane & 3;

    const int bm = blockIdx.y * BM;
    const int bn = blockIdx.x * BN;

    float acc[4][8][4];
#pragma unroll
    for (int i = 0; i < 4; i++)
#pragma unroll
        for (int j = 0; j < 8; j++)
#pragma unroll
            for (int r = 0; r < 4; r++) acc[i][j][r] = 0.0f;

    const int a_idx = (wm * 64 + (lane & 15)) * STRIDE + ((lane >> 4) << 2);
    const int b_idx = (wn * 64 + ((lane >> 4) << 3) + (lane & 7)) * STRIDE
                      + (((lane >> 3) & 1) << 2);

    auto load_a_chunk = [&](int kt, int stage, int it) {
        uint32_t* As = sm + stage * STAGE_H2;
        const int kh0 = kt * (BK / 2);
        int chunk = t + it * 256;
        int row = chunk >> 3, c = chunk & 7;
        cp_async16(&As[row * STRIDE + c * 4],
                   (const __half2*)A + (size_t)(bm + row) * (HID / 2) + kh0 + c * 4);
    };
    auto load_b_chunk = [&](int kt, int stage, int it) {
        uint32_t* Bs = sm + stage * STAGE_H2 + A_H2;
        const int kh0 = kt * (BK / 2);
        int chunk = t + it * 256;
        int row = chunk >> 3, c = chunk & 7;
        cp_async16(&Bs[row * STRIDE + c * 4],
                   (const __half2*)Wt + (size_t)(bn + row) * (HID / 2) + kh0 + c * 4);
    };
    auto load_tile = [&](int kt, int stage) {
#pragma unroll
        for (int it = 0; it < 4; it++) load_a_chunk(kt, stage, it);
#pragma unroll
        for (int it = 0; it < 8; it++) load_b_chunk(kt, stage, it);
        cp_commit();
    };

    auto step = [&](int kt, int stage) {
        asm volatile("cp.async.wait_group 1;\n" ::);
        __syncthreads();
        const int pstage = (stage == 0) ? 2 : stage - 1;
        const bool pf = (kt + 2 < NT);

        const int sbase = stage * STAGE_H2;
        const uint32_t a_addr0 = (uint32_t)__cvta_generic_to_shared(sm + sbase + a_idx);
        const uint32_t b_addr0 = (uint32_t)__cvta_generic_to_shared(sm + sbase + A_H2 + b_idx);

#pragma unroll
        for (int kk = 0; kk < 4; kk++) {
            const uint32_t koff = kk * 8 * 4;
            uint32_t af[4][4];
            uint32_t bf[4][4];
#pragma unroll
            for (int tm = 0; tm < 4; tm++)
                ldsm_x4(af[tm][0], af[tm][1], af[tm][2], af[tm][3],
                        a_addr0 + koff + tm * (16 * STRIDE * 4));
#pragma unroll
            for (int p = 0; p < 4; p++)
                ldsm_x4(bf[p][0], bf[p][1], bf[p][2], bf[p][3],
                        b_addr0 + koff + p * (16 * STRIDE * 4));
            if (pf) {
                load_a_chunk(kt + 2, pstage, kk);
                load_b_chunk(kt + 2, pstage, kk * 2);
                load_b_chunk(kt + 2, pstage, kk * 2 + 1);
            }
#pragma unroll
            for (int tm = 0; tm < 4; tm++)
#pragma unroll
                for (int tn = 0; tn < 8; tn++)
                    mma_f16(acc[tm][tn], af[tm], &bf[tn >> 1][(tn & 1) * 2]);
        }
        cp_commit();
    };

    load_tile(0, 0);
    load_tile(1, 1);

#pragma unroll 1
    for (int kt = 0; kt < 30; kt += 3) {
        step(kt,     0);
        step(kt + 1, 1);
        step(kt + 2, 2);
    }
    step(30, 0);
    step(31, 1);

    if (!fuse) {
#pragma unroll
        for (int tn = 0; tn < 8; tn++) {
            int c0 = bn + wn * 64 + tn * 8 + 2 * tg;
            float bv0 = __ldg(&bias[c0]);
            float bv1 = __ldg(&bias[c0 + 1]);
#pragma unroll
            for (int tm = 0; tm < 4; tm++) {
                int r0 = bm + wm * 64 + tm * 16 + g;
                __half2 v0 = __floats2half2_rn(fmaxf(acc[tm][tn][0] + bv0, 0.0f),
                                               fmaxf(acc[tm][tn][1] + bv1, 0.0f));
                __half2 v1 = __floats2half2_rn(fmaxf(acc[tm][tn][2] + bv0, 0.0f),
                                               fmaxf(acc[tm][tn][3] + bv1, 0.0f));
                *(__half2*)(C + (size_t)r0 * HID + c0) = v0;
                *(__half2*)(C + (size_t)(r0 + 8) * HID + c0) = v1;
            }
        }
    } else {
#pragma unroll
        for (int tm = 0; tm < 4; tm++) {
            float d0 = 0.0f, d1 = 0.0f;
#pragma unroll
            for (int tn = 0; tn < 8; tn++) {
                int c0 = bn + wn * 64 + tn * 8 + 2 * tg;
                float bv0 = __ldg(&bias[c0]);
                float bv1 = __ldg(&bias[c0 + 1]);
                float wv0 = __ldg(&w4[c0]);
                float wv1 = __ldg(&w4[c0 + 1]);
                d0 = fmaf(h_round(fmaxf(acc[tm][tn][0] + bv0, 0.0f)), wv0, d0);
                d0 = fmaf(h_round(fmaxf(acc[tm][tn][1] + bv1, 0.0f)), wv1, d0);
                d1 = fmaf(h_round(fmaxf(acc[tm][tn][2] + bv0, 0.0f)), wv0, d1);
                d1 = fmaf(h_round(fmaxf(acc[tm][tn][3] + bv1, 0.0f)), wv1, d1);
            }
            d0 += __shfl_xor_sync(0xFFFFFFFFu, d0, 1);
            d0 += __shfl_xor_sync(0xFFFFFFFFu, d0, 2);
            d1 += __shfl_xor_sync(0xFFFFFFFFu, d1, 1);
            d1 += __shfl_xor_sync(0xFFFFFFFFu, d1, 2);
            if (tg == 0) {
                int r0 = bm + wm * 64 + tm * 16 + g;
                if (r0 < M_ROWS)     atomicAdd(&g_amg[r0], d0);
                if (r0 + 8 < M_ROWS) atomicAdd(&g_amg[r0 + 8], d1);
            }
        }
    }
}

// ---------------------------------------------------------------------------
// Fused multigrid: one block upsamples its 4096-wide output slice level-by-
// level in shared memory (same O(1)-per-point dataflow as the 5-kernel chain).
// Stage st = 0..5; stage size n_st = (16384<<st)+1.  Stage 0 = relu(Ah + b4);
// stage st>0 applies interp + scatter of mg level st-1.  Stage 5 -> dout.
// ---------------------------------------------------------------------------
#define MG_CH 4096
__global__ void __launch_bounds__(256)
mg_fused(const int* __restrict__ nbrs, const float* __restrict__ b4,
         float* __restrict__ dout) {
    __shared__ float bufA[2054];   // stages 0, 2, 4  (max 2050)
    __shared__ float bufB[1032];   // stages 1, 3     (max 1027)
    __shared__ int   snb[40];

    const int t = threadIdx.x;
    const float b = __ldg(&b4[0]);
    if (t < 40) snb[t] = nbrs[t];

    // per-stage index ranges [start, end)
    int start[6], end[6];
    start[5] = blockIdx.x * MG_CH;
    end[5]   = min(start[5] + MG_CH, N_OUT);
#pragma unroll
    for (int st = 5; st >= 1; st--) {
        int n_lo = (16384 << (st - 1)) + 1;
        start[st - 1] = start[st] >> 1;
        end[st - 1]   = min(((end[st] - 1) >> 1) + 2, n_lo);
    }

    // stage 0: coarse Ah with bias+relu
    for (int q = start[0] + t; q < end[0]; q += 256)
        bufA[q - start[0]] = fmaxf(g_amg[40 + q] + b, 0.0f);
    __syncthreads();

#pragma unroll
    for (int st = 1; st <= 5; st++) {
        const int lvl = st - 1;
        const float* in = (st & 1) ? bufA : bufB;   // stage st-1 buffer
        float* out      = (st & 1) ? bufB : bufA;
        const int s_lo = start[st - 1];
        const int s_me = start[st];
        for (int i = s_me + t; i < end[st]; i += 256) {
            float v;
            if (i & 1) {
                int h = i >> 1;
                v = 0.5f * (in[h - s_lo] + in[h + 1 - s_lo]);
#pragma unroll
                for (int j = 0; j < 8; j++)
                    if (i == snb[lvl * 8 + j])
                        v = fmaxf(g_amg[8 * (4 - lvl) + j] + b, 0.0f);
            } else {
                v = in[(i >> 1) - s_lo];
            }
            if (st == 5) dout[i] = v;
            else         out[i - s_me] = v;
        }
        __syncthreads();
    }
}

// ---------------------------------------------------------------------------
// Launch
// ---------------------------------------------------------------------------
extern "C" void kernel_launch(void* const* d_in, const int* in_sizes, int n_in,
                              void* d_out, int out_size) {
    const float *xs, *w0, *b0, *w1, *b1, *w2, *b2, *w3, *b3, *w4, *b4;
    const int* nbrs;

    if (n_in >= 2 && in_sizes[1] == 40) {
        xs   = (const float*)d_in[0];
        nbrs = (const int*)d_in[1];
        w0 = (const float*)d_in[4];  b0 = (const float*)d_in[5];
        w1 = (const float*)d_in[6];  b1 = (const float*)d_in[7];
        w2 = (const float*)d_in[8];  b2 = (const float*)d_in[9];
        w3 = (const float*)d_in[10]; b3 = (const float*)d_in[11];
        w4 = (const float*)d_in[12]; b4 = (const float*)d_in[13];
    } else {
        xs   = (const float*)d_in[0];
        w0 = (const float*)d_in[1];  b0 = (const float*)d_in[2];
        w1 = (const float*)d_in[3];  b1 = (const float*)d_in[4];
        w2 = (const float*)d_in[5];  b2 = (const float*)d_in[6];
        w3 = (const float*)d_in[7];  b3 = (const float*)d_in[8];
        w4 = (const float*)d_in[9];  b4 = (const float*)d_in[10];
        nbrs = (const int*)d_in[11];
    }

    void* p_wh;
    cudaGetSymbolAddress(&p_wh, g_wh);
    __half* wh0 = (__half*)p_wh;
    __half* wh1 = wh0 + (size_t)HID * HID;
    __half* wh2 = wh1 + (size_t)HID * HID;

    cudaFuncSetAttribute(gemm_f16_kernel,
                         cudaFuncAttributeMaxDynamicSharedMemorySize, SMEM_BYTES);

    // Fused weight transpose + fp16 convert (all 3 layers, one launch)
    {
        dim3 gr(HID / 32, HID / 32, 3), bl(32, 8);
        transpose_half3<<<gr, bl>>>(w1, w2, w3, wh0);
    }

    // Layer 0 -> g_h0 (fp16), fused g_amg zeroing
    layer0_kernel<<<M_PAD / L0_ROWS, 256>>>(xs, w0, b0);

    // Hidden GEMMs; third fuses the final-layer GEMV into its epilogue
    dim3 grid(HID / BN, M_PAD / BM);  // (8, 129)
    gemm_f16_kernel<<<grid, 256, SMEM_BYTES>>>(wh0, b1, nullptr, 0, 0); // h0 -> h1
    gemm_f16_kernel<<<grid, 256, SMEM_BYTES>>>(wh1, b2, nullptr, 1, 0); // h1 -> h0
    gemm_f16_kernel<<<grid, 256, SMEM_BYTES>>>(wh2, b3, w4,      0, 1); // h0 -> g_amg

    // Entire multigrid reconstruction (bias+relu fused), one launch, smem-local
    mg_fused<<<(N_OUT + MG_CH - 1) / MG_CH, 256>>>(nbrs, b4, (float*)d_out);

    (void)out_size;
}